// round 14
// baseline (speedup 1.0000x reference)
#include <cuda_runtime.h>

// DepthwiseRREUp: groups=C*G conv_transpose2d, kernel=stride=2, pad=0.
// out[b,c,g, 2i+di, 2j+dj] = x[b,c,g,i,j] * rot90(dw[c], g)[di][dj]
//
// x:  [B=8, C=256, G=4, H=64, W=64] fp32     (128 MiB, read once)
// dw: [C=256, 1, 2, 2] fp32                  (cache-resident)
// out:[B, C, G, 128, 128] fp32               (512 MiB, written once)
//
// Combines the two best measured configs:
//   R12: block=512, no tail guard       -> 100.5 us, DRAM 79.5%
//   R8:  8-row tile (lowest alu/issue)  -> alu 6.6%, issue 10.6%
// Mapping: lane = output quad q (32 quads = one 128-float output row);
// thread covers 8 consecutive output rows (4 input rows) at quad q:
//   4x LDG.64 (256 B/warp contiguous) + 8x STG.128 (512 B/warp contiguous).
// Block covers 64 KB contiguous output; blocks sequential. Input read
// exactly once chip-wide. Five structural alternatives bracket an
// achieved-HBM plateau of ~6.3 TB/s for this 4:1 w:r mix; this round
// minimizes per-byte instruction overhead within the winning scheme.

__global__ void __launch_bounds__(512)
DepthwiseRREUp_40106404610493_kernel(const float2* __restrict__ x2,
                                     const float4* __restrict__ dw4,  // [C] of (a,b,c,d)
                                     float4* __restrict__ out4) {
    int t = blockIdx.x * 512 + threadIdx.x;

    int q     = t & 31;          // quad within output row == lane
    int rg    = t >> 5;          // row-group: 8 output rows
    int oi0   = (rg & 15) << 3;  // first output row (0..120, step 8)
    int plane = rg >> 4;         // linear (b,c,g)
    int g     = plane & 3;       // warp-uniform
    int c     = (plane >> 2) & 255;

    // Input rows oi0/2 .. oi0/2+3. Input plane = 2048 float2, 32 per row.
    const float2* xp = x2 + plane * 2048 + (oi0 >> 1) * 32 + q;
    float2 x0  = __ldcs(xp);
    float2 x1  = __ldcs(xp + 32);
    float2 x2v = __ldcs(xp + 64);
    float2 x3  = __ldcs(xp + 96);

    float4 w = dw4[c];  // a=w.x b=w.y c=w.z d=w.w (row-major 2x2)

    // numpy rot90 (CCW) k=g of [[a,b],[c,d]]:
    //   g=0: a b / c d    g=1: b d / a c
    //   g=2: d c / b a    g=3: c a / d b
    float f00, f01, f10, f11;
    switch (g) {
        case 0:  f00 = w.x; f01 = w.y; f10 = w.z; f11 = w.w; break;
        case 1:  f00 = w.y; f01 = w.w; f10 = w.x; f11 = w.z; break;
        case 2:  f00 = w.w; f01 = w.z; f10 = w.y; f11 = w.x; break;
        default: f00 = w.z; f01 = w.x; f10 = w.w; f11 = w.y; break;
    }

    // Output plane = 4096 float4, 32 per row.
    float4* op = out4 + plane * 4096 + oi0 * 32 + q;
    __stcs(op,       make_float4(x0.x * f00, x0.x * f01, x0.y * f00, x0.y * f01));
    __stcs(op + 32,  make_float4(x0.x * f10, x0.x * f11, x0.y * f10, x0.y * f11));
    __stcs(op + 64,  make_float4(x1.x * f00, x1.x * f01, x1.y * f00, x1.y * f01));
    __stcs(op + 96,  make_float4(x1.x * f10, x1.x * f11, x1.y * f10, x1.y * f11));
    __stcs(op + 128, make_float4(x2v.x * f00, x2v.x * f01, x2v.y * f00, x2v.y * f01));
    __stcs(op + 160, make_float4(x2v.x * f10, x2v.x * f11, x2v.y * f10, x2v.y * f11));
    __stcs(op + 192, make_float4(x3.x * f00, x3.x * f01, x3.y * f00, x3.y * f01));
    __stcs(op + 224, make_float4(x3.x * f10, x3.x * f11, x3.y * f10, x3.y * f11));
}

extern "C" void kernel_launch(void* const* d_in, const int* in_sizes, int n_in,
                              void* d_out, int out_size) {
    const float2* x2  = (const float2*)d_in[0];
    const float4* dw4 = (const float4*)d_in[1];
    float4* out4      = (float4*)d_out;

    int nthreads = out_size / 32;     // 4,194,304 tasks (8 output quads each)
    int blocks   = nthreads / 512;    // exact: 8192 blocks
    DepthwiseRREUp_40106404610493_kernel<<<blocks, 512>>>(x2, dw4, out4);
}

// round 16
// speedup vs baseline: 1.0140x; 1.0140x over previous
#include <cuda_runtime.h>

// DepthwiseRREUp: groups=C*G conv_transpose2d, kernel=stride=2, pad=0.
// out[b,c,g, 2i+di, 2j+dj] = x[b,c,g,i,j] * rot90(dw[c], g)[di][dj]
//
// x:  [B=8, C=256, G=4, H=64, W=64] fp32     (128 MiB, read once)
// dw: [C=256, 1, 2, 2] fp32                  (cache-resident)
// out:[B, C, G, 128, 128] fp32               (512 MiB, written once)
//
// NEW: Blackwell 256-bit stores (st.global.v8.f32) enable the input-centric
// mapping with perfect store coalescing. One thread per input float4:
//   1x LDG.128  (512 B/warp contiguous; input read exactly once)
//   2x STG.256  (each lane writes 32 B contiguous -> 1024 B/warp contiguous)
// 3 memory instructions per 64 B of output (champion R12 needs 6), and the
// largest per-request granularity the LSU supports — the one knob all
// previous rounds (all plateaued at ~6.3 TB/s) held fixed at 128-bit.

__global__ void __launch_bounds__(512)
DepthwiseRREUp_40106404610493_kernel(const float4* __restrict__ x4,
                                     const float4* __restrict__ dw4,  // [C] of (a,b,c,d)
                                     float* __restrict__ out) {
    int idx = blockIdx.x * 512 + threadIdx.x;   // input float4 id

    int j4    = idx & 15;         // float4 within 64-wide input row
    int i     = (idx >> 4) & 63;  // input row
    int plane = idx >> 10;        // linear (b,c,g)
    int g     = plane & 3;        // warp-uniform
    int c     = (plane >> 2) & 255;

    float4 xv = __ldcs(&x4[idx]);
    float4 w  = dw4[c];           // a=w.x b=w.y c=w.z d=w.w (row-major 2x2)

    // numpy rot90 (CCW) k=g of [[a,b],[c,d]]:
    //   g=0: a b / c d    g=1: b d / a c
    //   g=2: d c / b a    g=3: c a / d b
    float f00, f01, f10, f11;
    switch (g) {
        case 0:  f00 = w.x; f01 = w.y; f10 = w.z; f11 = w.w; break;
        case 1:  f00 = w.y; f01 = w.w; f10 = w.x; f11 = w.z; break;
        case 2:  f00 = w.w; f01 = w.z; f10 = w.y; f11 = w.x; break;
        default: f00 = w.z; f01 = w.x; f10 = w.w; f11 = w.y; break;
    }

    // Output plane = 16384 floats (128x128); rows 2i, 2i+1; cols 8*j4..8*j4+7.
    float* op = out + plane * 16384 + (2 * i) * 128 + j4 * 8;  // 32 B aligned

    asm volatile(
        "st.global.cs.v8.f32 [%0], {%1, %2, %3, %4, %5, %6, %7, %8};"
        :: "l"(op),
           "f"(xv.x * f00), "f"(xv.x * f01), "f"(xv.y * f00), "f"(xv.y * f01),
           "f"(xv.z * f00), "f"(xv.z * f01), "f"(xv.w * f00), "f"(xv.w * f01)
        : "memory");
    asm volatile(
        "st.global.cs.v8.f32 [%0], {%1, %2, %3, %4, %5, %6, %7, %8};"
        :: "l"(op + 128),
           "f"(xv.x * f10), "f"(xv.x * f11), "f"(xv.y * f10), "f"(xv.y * f11),
           "f"(xv.z * f10), "f"(xv.z * f11), "f"(xv.w * f10), "f"(xv.w * f11)
        : "memory");
}

extern "C" void kernel_launch(void* const* d_in, const int* in_sizes, int n_in,
                              void* d_out, int out_size) {
    const float4* x4  = (const float4*)d_in[0];
    const float4* dw4 = (const float4*)d_in[1];
    float* out        = (float*)d_out;

    int nthreads = in_sizes[0] / 4;   // 8,388,608 input float4s
    int blocks   = nthreads / 512;    // exact: 16384 blocks
    DepthwiseRREUp_40106404610493_kernel<<<blocks, 512>>>(x4, dw4, out);
}